// round 15
// baseline (speedup 1.0000x reference)
#include <cuda_runtime.h>
#include <cuda_fp16.h>
#include <cstdint>
#include <cstddef>

// out[4096,4096] = half(x)[4096,4096] @ half(W)^T + half(bias)
// E5M10 RNE quantize == __float2half_rn exactly for these inputs.
// Base sm_103 ISA (no tcgen05): cp.async + ldmatrix + mma.sync HMMA.
// R15: split-K=2 with deterministic in-kernel fixup. 2048 half-jobs on 304
//      slots -> 96% makespan fill (was 84%). Split0 stores partial+flag;
//      split1 polls flag, adds (p0+p1)+bias, stores out. Mainloop = R10.

#define ND 4096

static constexpr int BM = 128;
static constexpr int BN = 128;
static constexpr int BK = 64;            // 64 halves = 128 B rows
static constexpr int STAGES = 3;
static constexpr int NTHREADS = 128;     // 4 warps
static constexpr int KSPLIT = 2;
static constexpr int KLEN = ND / KSPLIT; // 2048
static constexpr int NTILES = (ND / BM) * (ND / BN);   // 1024

static constexpr int A_BYTES = BM * 128;              // 16 KB
static constexpr int B_BYTES = BN * 128;              // 16 KB
static constexpr int STAGE_BYTES = A_BYTES + B_BYTES; // 32 KB
static constexpr int SMEM_BYTES = STAGES * STAGE_BYTES; // 96 KB -> 2 CTAs/SM

// __device__ scratch (no runtime allocation allowed)
__device__ __half g_qA[(size_t)ND * ND];
__device__ __half g_qB[(size_t)ND * ND];
__device__ float  g_qbias[ND];
__device__ float  g_part[(size_t)NTILES * BM * BN];   // 64 MB split-0 partials
__device__ unsigned int g_flag[NTILES];

// ---------------- helpers ----------------
__device__ __forceinline__ uint32_t smem_u32(const void* p) {
    uint32_t a;
    asm("{ .reg .u64 t; cvta.to.shared.u64 t, %1; cvt.u32.u64 %0, t; }" : "=r"(a) : "l"(p));
    return a;
}

__device__ __forceinline__ void ldmatrix_x4(uint32_t& r0, uint32_t& r1, uint32_t& r2,
                                            uint32_t& r3, uint32_t addr) {
    asm volatile("ldmatrix.sync.aligned.m8n8.x4.shared.b16 {%0,%1,%2,%3}, [%4];"
                 : "=r"(r0), "=r"(r1), "=r"(r2), "=r"(r3) : "r"(addr));
}

__device__ __forceinline__ void mma_16816(float* c, const uint32_t* a,
                                          uint32_t b0, uint32_t b1) {
    asm volatile(
        "mma.sync.aligned.m16n8k16.row.col.f32.f16.f16.f32 "
        "{%0,%1,%2,%3}, {%4,%5,%6,%7}, {%8,%9}, {%0,%1,%2,%3};"
        : "+f"(c[0]), "+f"(c[1]), "+f"(c[2]), "+f"(c[3])
        : "r"(a[0]), "r"(a[1]), "r"(a[2]), "r"(a[3]), "r"(b0), "r"(b1));
}

// ---------------- quantize pass (also resets split-K flags) ----------------
__device__ __forceinline__ uint32_t h2_bits(__half2 h) {
    union { __half2 h; uint32_t u; } cv;
    cv.h = h;
    return cv.u;
}

__device__ __forceinline__ uint4 q8(float4 v0, float4 v1) {
    uint4 o;
    o.x = h2_bits(__floats2half2_rn(v0.x, v0.y));
    o.y = h2_bits(__floats2half2_rn(v0.z, v0.w));
    o.z = h2_bits(__floats2half2_rn(v1.x, v1.y));
    o.w = h2_bits(__floats2half2_rn(v1.z, v1.w));
    return o;
}

__global__ void __launch_bounds__(256) quantize_kernel(
    const float* __restrict__ x, const float* __restrict__ w, const float* __restrict__ b) {
    const size_t i = (size_t)blockIdx.x * blockDim.x + threadIdx.x;
    const size_t T = (size_t)gridDim.x * blockDim.x;       // 1,048,576
    const float4* __restrict__ x4 = (const float4*)x;
    const float4* __restrict__ w4 = (const float4*)w;
    uint4* __restrict__ qa4 = (uint4*)g_qA;
    uint4* __restrict__ qb4 = (uint4*)g_qB;

    const size_t j0 = i;
    const size_t j1 = i + T;
    float4 a0 = __ldcs(&x4[2 * j0]),     a1 = __ldcs(&x4[2 * j0 + 1]);
    float4 a2 = __ldcs(&x4[2 * j1]),     a3 = __ldcs(&x4[2 * j1 + 1]);
    float4 b0 = __ldcs(&w4[2 * j0]),     b1 = __ldcs(&w4[2 * j0 + 1]);
    float4 b2 = __ldcs(&w4[2 * j1]),     b3 = __ldcs(&w4[2 * j1 + 1]);

    qa4[j0] = q8(a0, a1);
    qa4[j1] = q8(a2, a3);
    qb4[j0] = q8(b0, b1);
    qb4[j1] = q8(b2, b3);

    if (i < ND) g_qbias[i] = __half2float(__float2half_rn(b[i]));
    if (i < NTILES) g_flag[i] = 0u;
}

// ---------------- GEMM (R10 mainloop, split-K epilogue) ----------------
__device__ __forceinline__ void load_stage(uint32_t stage_base, const __half* Ag,
                                           const __half* Bg, int kbase, int tid) {
#pragma unroll
    for (int i = 0; i < 16; ++i) {
        int c = tid + i * NTHREADS;          // 0..2047
        bool isA = c < 1024;
        int cc = c & 1023;
        int row = cc >> 3;
        int ch = cc & 7;
        uint32_t dst = stage_base + (isA ? 0u : (uint32_t)A_BYTES)
                     + (uint32_t)(row * 128) + (uint32_t)((ch ^ (row & 7)) << 4);
        const __half* src = (isA ? Ag : Bg) + (size_t)row * ND + kbase + ch * 8;
        asm volatile("cp.async.cg.shared.global [%0], [%1], 16;" :: "r"(dst), "l"(src));
    }
    asm volatile("cp.async.commit_group;" ::: "memory");
}

__global__ void __launch_bounds__(NTHREADS, 2)
qgemm_kernel(float* __restrict__ out) {
    extern __shared__ char smem_raw[];
    const uint32_t smem_base = smem_u32(smem_raw);

    const int tid = threadIdx.x;
    const int wid = tid >> 5;        // 0..3
    const int lane = tid & 31;
    const int bx = blockIdx.x;       // 0..63: tile_n*2 + split (pairs adjacent)
    const int tile_n = bx >> 1;
    const int split = bx & 1;
    const int tile_m = blockIdx.y;   // 0..31
    const int tidx = tile_m * 32 + tile_n;

    const int wm = wid & 1;          // 2 warps along M -> 64 rows each
    const int wn = wid >> 1;         // 2 warps along N -> 64 cols each

    const __half* Ag = g_qA + (size_t)tile_m * BM * ND + split * KLEN;
    const __half* Bg = g_qB + (size_t)tile_n * BN * ND + split * KLEN;

    // Per-lane ldmatrix address components. XOR term depends only on lane.
    const uint32_t xorv = (uint32_t)(lane & 7);
    uint32_t a_row_off[4];
#pragma unroll
    for (int f = 0; f < 4; ++f)
        a_row_off[f] = (uint32_t)((wm * 64 + f * 16 + (lane & 15)) * 128);
    const uint32_t a_ch_base = (uint32_t)(lane >> 4);
    uint32_t b_row_off[4];
#pragma unroll
    for (int h = 0; h < 4; ++h)
        b_row_off[h] = (uint32_t)((wn * 64 + h * 16 + (lane & 7) + ((lane >> 4) & 1) * 8) * 128);
    const uint32_t b_ch_base = (uint32_t)((lane >> 3) & 1);

    float acc[4][8][4];
#pragma unroll
    for (int f = 0; f < 4; ++f)
#pragma unroll
        for (int g = 0; g < 8; ++g)
#pragma unroll
            for (int r = 0; r < 4; ++r) acc[f][g][r] = 0.0f;

    constexpr int NIT = KLEN / BK;   // 32

    // Prologue: 2 stages in flight
    load_stage(smem_base + 0 * STAGE_BYTES, Ag, Bg, 0 * BK, tid);
    load_stage(smem_base + 1 * STAGE_BYTES, Ag, Bg, 1 * BK, tid);

    int buf = 0;
    for (int it = 0; it < NIT; ++it) {
        if (it <= NIT - 2) asm volatile("cp.async.wait_group 1;" ::: "memory");
        else               asm volatile("cp.async.wait_group 0;" ::: "memory");
        __syncthreads();

        const int nl = it + 2;
        if (nl < NIT) {
            int nb = buf + 2; if (nb >= STAGES) nb -= STAGES;
            load_stage(smem_base + (uint32_t)(nb * STAGE_BYTES), Ag, Bg, nl * BK, tid);
        }

        const uint32_t sA = smem_base + (uint32_t)(buf * STAGE_BYTES);
        const uint32_t sB = sA + A_BYTES;

#pragma unroll
        for (int ks = 0; ks < BK / 16; ++ks) {
            uint32_t a[4][4];
#pragma unroll
            for (int f = 0; f < 4; ++f) {
                uint32_t ch = (uint32_t)(ks * 2) + a_ch_base;
                ldmatrix_x4(a[f][0], a[f][1], a[f][2], a[f][3],
                            sA + a_row_off[f] + ((ch ^ xorv) << 4));
            }
            uint32_t bfrag[4][4];
#pragma unroll
            for (int h = 0; h < 4; ++h) {
                uint32_t ch = (uint32_t)(ks * 2) + b_ch_base;
                ldmatrix_x4(bfrag[h][0], bfrag[h][1], bfrag[h][2], bfrag[h][3],
                            sB + b_row_off[h] + ((ch ^ xorv) << 4));
            }
#pragma unroll
            for (int f = 0; f < 4; ++f)
#pragma unroll
                for (int g = 0; g < 8; ++g)
                    mma_16816(acc[f][g], a[f], bfrag[g >> 1][(g & 1) * 2],
                              bfrag[g >> 1][(g & 1) * 2 + 1]);
        }

        if (++buf == STAGES) buf = 0;
    }

    // ---------------- split-K epilogue ----------------
    const int rl_base = wm * 64 + (lane >> 2);           // local row
    const int cl_base = wn * 64 + 2 * (lane & 3);        // local col
    float* part = g_part + (size_t)tidx * (BM * BN);

    if (split == 0) {
        // Producer: store partial tile, fence, raise flag.
#pragma unroll
        for (int f = 0; f < 4; ++f) {
#pragma unroll
            for (int g = 0; g < 8; ++g) {
                const int cl = cl_base + g * 8;
                const int rl = rl_base + f * 16;
                float2 v0, v1;
                v0.x = acc[f][g][0];  v0.y = acc[f][g][1];
                v1.x = acc[f][g][2];  v1.y = acc[f][g][3];
                *(float2*)(part + (size_t)rl * BN + cl) = v0;
                *(float2*)(part + (size_t)(rl + 8) * BN + cl) = v1;
            }
        }
        __syncthreads();                 // all partial stores issued CTA-wide
        if (tid == 0) {
            __threadfence();             // publish partials before flag
            atomicExch(&g_flag[tidx], 1u);
        }
    } else {
        // Reducer: wait for producer's partial, then out = (p0 + p1) + bias.
        if (tid == 0) {
            while (atomicAdd(&g_flag[tidx], 0u) == 0u) __nanosleep(64);
        }
        __syncthreads();                 // leader-acquire + barrier orders reads
        const int row_base = tile_m * BM;
        const int col_base = tile_n * BN;
#pragma unroll
        for (int f = 0; f < 4; ++f) {
#pragma unroll
            for (int g = 0; g < 8; ++g) {
                const int cl = cl_base + g * 8;
                const int rl = rl_base + f * 16;
                const float2 bv = *(const float2*)(g_qbias + col_base + cl);
                const float2 p0 = *(const float2*)(part + (size_t)rl * BN + cl);
                const float2 p1 = *(const float2*)(part + (size_t)(rl + 8) * BN + cl);
                float2 v0, v1;
                v0.x = (p0.x + acc[f][g][0]) + bv.x;  v0.y = (p0.y + acc[f][g][1]) + bv.y;
                v1.x = (p1.x + acc[f][g][2]) + bv.x;  v1.y = (p1.y + acc[f][g][3]) + bv.y;
                *(float2*)(out + (size_t)(row_base + rl) * ND + col_base + cl) = v0;
                *(float2*)(out + (size_t)(row_base + rl + 8) * ND + col_base + cl) = v1;
            }
        }
    }
}

// ---------------- launch ----------------
extern "C" void kernel_launch(void* const* d_in, const int* in_sizes, int n_in,
                              void* d_out, int out_size) {
    const float* x = (const float*)d_in[0];
    const float* w = (const float*)d_in[1];
    const float* b = (const float*)d_in[2];
    float* out = (float*)d_out;

    quantize_kernel<<<4096, 256>>>(x, w, b);

    cudaFuncSetAttribute(qgemm_kernel, cudaFuncAttributeMaxDynamicSharedMemorySize, SMEM_BYTES);
    dim3 grid(2 * ND / BN, ND / BM);   // (64, 32) = 2048 CTAs (tile_n x split, tile_m)
    qgemm_kernel<<<grid, NTHREADS, SMEM_BYTES>>>(out);
}